// round 15
// baseline (speedup 1.0000x reference)
#include <cuda_runtime.h>
#include <cuda_fp16.h>
#include <math.h>
#include <stdint.h>

#define B_ 2
#define T_ 2048
#define C_ 2048
#define NV_ 32
#define NHK_ 16
#define DK_ 128
#define DV_ 128
#define KEY_DIM_ 2048
#define VAL_DIM_ 4096
#define CONV_DIM_ 8192
#define BT_ (B_*T_)
#define LCH 64
#define NCH (T_/LCH)
#define SPLITV 4
#define DVS (DV_/SPLITV)
#define CTT 8

typedef unsigned long long ull;

// ---------------- scratch (static device globals; no allocation) ----------------
__device__ float g_qkv [BT_*CONV_DIM_];
__device__ float g_z   [BT_*VAL_DIM_];
__device__ float g_q   [BT_*KEY_DIM_];
__device__ float g_k   [BT_*KEY_DIM_];
__device__ float g_v   [BT_*VAL_DIM_];
__device__ float g_beta[BT_*NV_];
__device__ float g_gg  [BT_*NV_];
__device__ float g_o   [BT_*VAL_DIM_];
__device__ float g_qk  [(size_t)B_*NHK_*NCH*LCH*LCH];

__device__ __half g_xh [BT_*C_];
__device__ __half g_Wqh[CONV_DIM_*C_];
__device__ __half g_Wzh[VAL_DIM_*C_];
__device__ __half g_Woh[C_*VAL_DIM_];
__device__ __half g_oh [BT_*VAL_DIM_];

// ---------------- helpers ----------------
__device__ __forceinline__ uint32_t smem_u32(const void* p) {
    uint32_t a;
    asm("{ .reg .u64 t; cvta.to.shared.u64 t, %1; cvt.u32.u64 %0, t; }" : "=r"(a) : "l"(p));
    return a;
}
__device__ __forceinline__ void ldsm_x4(uint32_t& r0, uint32_t& r1, uint32_t& r2, uint32_t& r3, uint32_t addr) {
    asm volatile("ldmatrix.sync.aligned.m8n8.x4.shared.b16 {%0,%1,%2,%3}, [%4];"
                 : "=r"(r0), "=r"(r1), "=r"(r2), "=r"(r3) : "r"(addr));
}
__device__ __forceinline__ void mma16816(float* c, uint32_t a0, uint32_t a1, uint32_t a2, uint32_t a3,
                                         uint32_t b0, uint32_t b1) {
    asm volatile("mma.sync.aligned.m16n8k16.row.col.f32.f16.f16.f32 "
                 "{%0,%1,%2,%3}, {%4,%5,%6,%7}, {%8,%9}, {%0,%1,%2,%3};"
                 : "+f"(c[0]), "+f"(c[1]), "+f"(c[2]), "+f"(c[3])
                 : "r"(a0), "r"(a1), "r"(a2), "r"(a3), "r"(b0), "r"(b1));
}
#define CP_ASYNC16(dst, src) asm volatile("cp.async.cg.shared.global [%0], [%1], 16;" :: "r"(dst), "l"(src))
#define CP_COMMIT()          asm volatile("cp.async.commit_group;" ::: "memory")
#define CP_WAIT1()           asm volatile("cp.async.wait_group 1;" ::: "memory")

// ---- packed fp32x2 ----
__device__ __forceinline__ ull bcast2(float s) {
    ull r; asm("mov.b64 %0, {%1, %1};" : "=l"(r) : "f"(s)); return r;
}
__device__ __forceinline__ void fma2(ull& a, ull s, ull b) {
    asm("fma.rn.f32x2 %0, %1, %2, %0;" : "+l"(a) : "l"(s), "l"(b));
}
__device__ __forceinline__ void mul2(ull& a, ull b) {
    asm("mul.rn.f32x2 %0, %0, %1;" : "+l"(a) : "l"(b));
}
__device__ __forceinline__ float2 unpack2(ull a) {
    float2 f; asm("mov.b64 {%0, %1}, %2;" : "=f"(f.x), "=f"(f.y) : "l"(a)); return f;
}

// ---------------- fp16 HGEMM: block 128x128, 8 warps (2Mx4N), warp 64x32 ----------------
// K-tile 64, 3-stage cp.async, one barrier per tile.
#define HSTG (128 * 72)
__global__ __launch_bounds__(256, 2)
void hgemm_nt(const __half* __restrict__ A, const __half* __restrict__ Bm,
              float* __restrict__ C, int N, int K, int rowBase)
{
    extern __shared__ __half hsm[];
    __half* AsP = hsm;
    __half* BsP = hsm + 3 * HSTG;

    int tid = threadIdx.x;
    int lane = tid & 31, wid = tid >> 5;
    int wm = wid & 1, wn = wid >> 1;
    int m0w = wm * 64, n0w = wn * 32;
    int row0 = rowBase + blockIdx.y * 128, col0 = blockIdx.x * 128;

    uint32_t aBase = smem_u32(AsP);
    uint32_t bBase = smem_u32(BsP);

    float acc[4][4][4];
#pragma unroll
    for (int i = 0; i < 4; i++)
#pragma unroll
        for (int j = 0; j < 4; j++)
#pragma unroll
            for (int e = 0; e < 4; e++) acc[i][j][e] = 0.f;

    const int NT = K >> 6;

    auto issue = [&](int kt, int s) {
        int k0 = kt << 6;
#pragma unroll
        for (int i = 0; i < 4; i++) {
            int f = tid + (i << 8);
            int r = f >> 3, c = (f & 7) << 3;
            CP_ASYNC16(aBase + ((s * HSTG + r * 72 + c) << 1),
                       A + (size_t)(row0 + r) * K + k0 + c);
        }
#pragma unroll
        for (int i = 0; i < 4; i++) {
            int f = tid + (i << 8);
            int r = f >> 3, c = (f & 7) << 3;
            CP_ASYNC16(bBase + ((s * HSTG + r * 72 + c) << 1),
                       Bm + (size_t)(col0 + r) * K + k0 + c);
        }
        CP_COMMIT();
    };

    issue(0, 0);
    issue(1, 1);

    for (int kt = 0; kt < NT; kt++) {
        CP_WAIT1();
        __syncthreads();
        if (kt + 2 < NT) issue(kt + 2, (kt + 2) % 3);
        int s = kt % 3;
#pragma unroll
        for (int kk = 0; kk < 64; kk += 16) {
            uint32_t a[4][4], b[4][2];
#pragma unroll
            for (int i = 0; i < 4; i++) {
                int r = m0w + i * 16 + (lane & 15);
                int c = kk + ((lane >> 4) << 3);
                ldsm_x4(a[i][0], a[i][1], a[i][2], a[i][3],
                        aBase + ((s * HSTG + r * 72 + c) << 1));
            }
#pragma unroll
            for (int j = 0; j < 2; j++) {
                int q = lane >> 3, rr = lane & 7;
                int r = n0w + j * 16 + ((q >> 1) << 3) + rr;
                int c = kk + ((q & 1) << 3);
                uint32_t t0, t1, t2, t3;
                ldsm_x4(t0, t1, t2, t3, bBase + ((s * HSTG + r * 72 + c) << 1));
                b[2*j][0] = t0; b[2*j][1] = t1; b[2*j+1][0] = t2; b[2*j+1][1] = t3;
            }
#pragma unroll
            for (int i = 0; i < 4; i++)
#pragma unroll
                for (int j = 0; j < 4; j++)
                    mma16816(acc[i][j], a[i][0], a[i][1], a[i][2], a[i][3], b[j][0], b[j][1]);
        }
    }

#pragma unroll
    for (int i = 0; i < 4; i++) {
        int r = row0 + m0w + i * 16 + (lane >> 2);
#pragma unroll
        for (int j = 0; j < 4; j++) {
            int c = col0 + n0w + j * 8 + ((lane & 3) << 1);
            *(float2*)&C[(size_t)r * N + c]       = make_float2(acc[i][j][0], acc[i][j][1]);
            *(float2*)&C[(size_t)(r + 8) * N + c] = make_float2(acc[i][j][2], acc[i][j][3]);
        }
    }
}

// ---------------- fp32 -> fp16 converters (two-tensor fused) ----------------
__global__ void cvt2(const float* __restrict__ s0, __half* __restrict__ d0, int n0,
                     const float* __restrict__ s1, __half* __restrict__ d1, int n1)
{
    int i = blockIdx.x * blockDim.x + threadIdx.x;
    const float* src; __half* dst; int off;
    if (i < n0)           { src = s0; dst = d0; off = i; }
    else if (i < n0 + n1) { src = s1; dst = d1; off = i - n0; }
    else return;
    float4 v = ((const float4*)src)[off];
    union { __half h[4]; uint2 u; } p;
    p.h[0] = __float2half_rn(v.x); p.h[1] = __float2half_rn(v.y);
    p.h[2] = __float2half_rn(v.z); p.h[3] = __float2half_rn(v.w);
    ((uint2*)dst)[off] = p.u;
}

// ---------------- fused fp32 GEMM for b|a + beta/g finalize ----------------
__global__ __launch_bounds__(256)
void sgemm_ba_fused(const float* __restrict__ A, const float* __restrict__ Wb,
                    const float* __restrict__ Wa, const float* __restrict__ dt_bias,
                    const float* __restrict__ A_log)
{
    __shared__ float As[16][128];
    __shared__ float Bs[16][64];
    int tid = threadIdx.x;
    int tx = tid & 15, ty = tid >> 4;
    int row0 = blockIdx.y * 128;

    float acc[8][4];
#pragma unroll
    for (int m = 0; m < 8; m++)
#pragma unroll
        for (int n = 0; n < 4; n++) acc[m][n] = 0.f;

    for (int kt = 0; kt < C_; kt += 16) {
#pragma unroll
        for (int i = 0; i < 2; i++) {
            int f = tid + i * 256;
            int r = f >> 2, c4 = (f & 3) << 2;
            float4 av = *(const float4*)(A + (size_t)(row0 + r) * C_ + kt + c4);
            As[c4][r] = av.x; As[c4+1][r] = av.y; As[c4+2][r] = av.z; As[c4+3][r] = av.w;
        }
        {
            int r = tid >> 2, c4 = (tid & 3) << 2;
            if (r < 64) {
                const float* src = (r < 32) ? (Wb + (size_t)r * C_) : (Wa + (size_t)(r - 32) * C_);
                float4 bv = *(const float4*)(src + kt + c4);
                Bs[c4][r] = bv.x; Bs[c4+1][r] = bv.y; Bs[c4+2][r] = bv.z; Bs[c4+3][r] = bv.w;
            }
        }
        __syncthreads();
#pragma unroll
        for (int k = 0; k < 16; k++) {
            float ra[8], rb[4];
            *(float4*)&ra[0] = *(float4*)&As[k][ty * 8];
            *(float4*)&ra[4] = *(float4*)&As[k][ty * 8 + 4];
            *(float4*)&rb[0] = *(float4*)&Bs[k][tx * 4];
#pragma unroll
            for (int m = 0; m < 8; m++)
#pragma unroll
                for (int n = 0; n < 4; n++) acc[m][n] += ra[m] * rb[n];
        }
        __syncthreads();
    }
#pragma unroll
    for (int m = 0; m < 8; m++) {
        int bt = row0 + ty * 8 + m;
#pragma unroll
        for (int n = 0; n < 4; n++) {
            int col = tx * 4 + n;
            float v = acc[m][n];
            if (col < 32) {
                g_beta[bt * NV_ + col] = 1.f / (1.f + expf(-v));
            } else {
                int h = col - 32;
                float a = v + dt_bias[h];
                float sp = (a > 20.f) ? a : log1pf(expf(a));
                g_gg[bt * NV_ + h] = -expf(A_log[h]) * sp;
            }
        }
    }
}

// ---------------- causal depthwise conv(K=4) + silu, per-batch ----------------
__global__ __launch_bounds__(256)
void conv_kernel(const float* __restrict__ conv_w,
                 const float* __restrict__ conv_state,
                 const int* __restrict__ input_pos, int bsel)
{
    int b = bsel;
    int t0 = blockIdx.x * CTT;
    int tid = threadIdx.x;
    float keep = (input_pos[0] == 0) ? 0.f : 1.f;

    for (int d = tid; d < CONV_DIM_; d += 256) {
        float4 w = *(const float4*)(conv_w + (size_t)d * 4);
        float xv[CTT + 3];
#pragma unroll
        for (int j = 0; j < CTT + 3; j++) {
            int tt = t0 - 3 + j;
            if (tt >= 0) xv[j] = g_qkv[(size_t)(b * T_ + tt) * CONV_DIM_ + d];
            else         xv[j] = keep * conv_state[((size_t)b * CONV_DIM_ + d) * 4 + (tt + 4)];
        }
#pragma unroll
        for (int to = 0; to < CTT; to++) {
            float acc = w.x * xv[to] + w.y * xv[to+1] + w.z * xv[to+2] + w.w * xv[to+3];
            float s = acc / (1.f + expf(-acc));
            size_t bt = (size_t)(b * T_ + t0 + to);
            if (d < 2048)      g_q[bt * KEY_DIM_ + d] = s;
            else if (d < 4096) g_k[bt * KEY_DIM_ + (d - 2048)] = s;
            else               g_v[bt * VAL_DIM_ + (d - 4096)] = s;
        }
    }
}

// normalize one 128-wide row held in smem (fp32)
__device__ __forceinline__ void norm_row_smem(float* row)
{
    float ss = 0.f;
#pragma unroll
    for (int c = 0; c < 32; c++) {
        float4 v = *(float4*)&row[c * 4];
        ss += v.x*v.x + v.y*v.y + v.z*v.z + v.w*v.w;
    }
    float inv = 1.f / fmaxf(sqrtf(ss), 1e-12f);
#pragma unroll
    for (int c = 0; c < 32; c++) {
        float4 v = *(float4*)&row[c * 4];
        v.x *= inv; v.y *= inv; v.z *= inv; v.w *= inv;
        *(float4*)&row[c * 4] = v;
    }
}

// ---------------- QK precompute: normalize q/k (write back) + raw scores ----------------
__global__ __launch_bounds__(256)
void qk_kernel(int bsel)
{
    extern __shared__ float qsm[];
    float* sq = qsm;
    float* sk = qsm + 64 * 132;

    int bidx = blockIdx.x;               // hk*NCH + ch
    int ch = bidx % NCH;
    int hk = bidx / NCH;
    int b  = bsel;
    int t0 = ch * LCH;
    int tid = threadIdx.x;
    int tx = tid & 15, ty = tid >> 4;

    for (int f = tid; f < 64 * 32; f += 256) {
        int r = f >> 5, c = (f & 31) * 4;
        *(float4*)&sq[r * 132 + c] = *(const float4*)(g_q + (size_t)(b * T_ + t0 + r) * KEY_DIM_ + hk * DK_ + c);
        *(float4*)&sk[r * 132 + c] = *(const float4*)(g_k + (size_t)(b * T_ + t0 + r) * KEY_DIM_ + hk * DK_ + c);
    }
    __syncthreads();
    if (tid < 128) {
        float* row = (tid < 64) ? (sq + tid * 132) : (sk + (tid - 64) * 132);
        norm_row_smem(row);
    }
    __syncthreads();
    // write normalized q/k back so recur skips normalization
    for (int f = tid; f < 64 * 32; f += 256) {
        int r = f >> 5, c = (f & 31) * 4;
        *(float4*)(g_q + (size_t)(b * T_ + t0 + r) * KEY_DIM_ + hk * DK_ + c) = *(float4*)&sq[r * 132 + c];
        *(float4*)(g_k + (size_t)(b * T_ + t0 + r) * KEY_DIM_ + hk * DK_ + c) = *(float4*)&sk[r * 132 + c];
    }

    ull acc2[4][4];
#pragma unroll
    for (int a = 0; a < 4; a++)
#pragma unroll
        for (int c = 0; c < 4; c++) acc2[a][c] = 0ull;

    if (tx * 4 <= ty * 4 + 3) {
        for (int k4 = 0; k4 < DK_; k4 += 4) {
            ull kb0[4], kb1[4];
#pragma unroll
            for (int c = 0; c < 4; c++) {
                kb0[c] = *(ull*)&sk[(tx * 4 + c) * 132 + k4];
                kb1[c] = *(ull*)&sk[(tx * 4 + c) * 132 + k4 + 2];
            }
#pragma unroll
            for (int a = 0; a < 4; a++) {
                ull qa0 = *(ull*)&sq[(ty * 4 + a) * 132 + k4];
                ull qa1 = *(ull*)&sq[(ty * 4 + a) * 132 + k4 + 2];
#pragma unroll
                for (int c = 0; c < 4; c++) {
                    fma2(acc2[a][c], qa0, kb0[c]);
                    fma2(acc2[a][c], qa1, kb1[c]);
                }
            }
        }
    }
    float* dst = g_qk + ((size_t)((b * NHK_ + hk) * NCH + ch)) * (LCH * LCH);
#pragma unroll
    for (int a = 0; a < 4; a++) {
        float r[4];
#pragma unroll
        for (int c = 0; c < 4; c++) {
            float2 p = unpack2(acc2[a][c]);
            r[c] = p.x + p.y;
        }
        *(float4*)&dst[(ty * 4 + a) * 64 + tx * 4] = make_float4(r[0], r[1], r[2], r[3]);
    }
}

// ---------------- recurrence (512 thr, f32x2), SPLITV=4 (DVS=32), per-batch ----------------
// tx = tid&7 (8 col groups x 4 = 32 cols), ty = tid>>3 (64): 1 out row, 2 state rows per thread.
__global__ __launch_bounds__(512)
void recur_kernel(const float* __restrict__ rstate, const int* __restrict__ input_pos, int bsel)
{
    extern __shared__ float sm[];
    float* sq = sm;                   // 64*132
    float* sk = sq + 64 * 132;        // 64*132
    float* sv = sk + 64 * 132;        // 64*36
    float* sA = sv + 64 * 36;         // 64*68
    float* sS = sA + 64 * 68;         // 128*36
    float* sG = sS + 128 * 36;        // 64
    float* sB = sG + 64;              // 64
    float* sW = sB + 64;              // 64

    int bidx = blockIdx.x;            // vs + 4*h
    int vs = bidx & 3;
    int h  = bidx >> 2;
    int b  = bsel;
    int hk = h >> 1;
    int tid = threadIdx.x;
    int tx = tid & 7, ty = tid >> 3;  // tx: 8 col groups, ty: 0..63
    float keep = (input_pos[0] == 0) ? 0.f : 1.f;

    // state rows ty*2, ty*2+1; cols tx*4..+3
#pragma unroll
    for (int j = 0; j < 2; j++) {
        int kk = ty * 2 + j;
        float4 v4 = *(const float4*)(rstate + (((size_t)(b * NV_ + h)) * DK_ + kk) * DV_ + vs * DVS + tx * 4);
        v4.x *= keep; v4.y *= keep; v4.z *= keep; v4.w *= keep;
        *(float4*)&sS[kk * 36 + tx * 4] = v4;
    }

    const float* qkBase = g_qk + ((size_t)(b * NHK_ + hk) * NCH) * (LCH * LCH);

    for (int ch = 0; ch < NCH; ch++) {
        int t0 = ch * LCH;
        __syncthreads();
        for (int f = tid; f < 64 * 32; f += 512) {
            int r = f >> 5, c = (f & 31) * 4;
            *(float4*)&sq[r * 132 + c] = *(const float4*)(g_q + (size_t)(b * T_ + t0 + r) * KEY_DIM_ + hk * DK_ + c);
            *(float4*)&sk[r * 132 + c] = *(const float4*)(g_k + (size_t)(b * T_ + t0 + r) * KEY_DIM_ + hk * DK_ + c);
        }
        {   // sv: 64 rows x 32 cols = 512 float4
            int r = tid >> 3, c = (tid & 7) * 4;
            *(float4*)&sv[r * 36 + c] = *(const float4*)(g_v + (size_t)(b * T_ + t0 + r) * VAL_DIM_ + h * DV_ + vs * DVS + c);
        }
        if (tid < 64) {
            sB[tid] = g_beta[(b * T_ + t0 + tid) * NV_ + h];
            sG[tid] = g_gg  [(b * T_ + t0 + tid) * NV_ + h];
        }
        __syncthreads();
        if (tid == 0) {
            float run = 0.f;
            for (int i = 0; i < LCH; i++) { run += sG[i]; sG[i] = run; }
        }
        __syncthreads();
        if (tid < 64) {
            float df = sG[63] - sG[tid];
            sW[tid] = (df > -30.f) ? expf(df) * sB[tid] : 0.f;
        }

        // sA[t][i] = QK[t][i] * exp(Gt - Gi) * beta_i, masked i<=t. 8 elems/thread.
        {
            const float* qkT = qkBase + (size_t)ch * (LCH * LCH);
            int f0 = tid * 8;
            int t = f0 >> 6, i0 = f0 & 63;
            float gt = sG[t];
            float4 qa = *(const float4*)(qkT + t * 64 + i0);
            float4 qb = *(const float4*)(qkT + t * 64 + i0 + 4);
            float r[8] = {qa.x, qa.y, qa.z, qa.w, qb.x, qb.y, qb.z, qb.w};
#pragma unroll
            for (int j = 0; j < 8; j++) {
                int i = i0 + j;
                float d = gt - sG[i];
                r[j] = (i <= t && d > -30.f) ? r[j] * expf(d) * sB[i] : 0.f;
            }
            *(float4*)&sA[t * 68 + i0]     = make_float4(r[0], r[1], r[2], r[3]);
            *(float4*)&sA[t * 68 + i0 + 4] = make_float4(r[4], r[5], r[6], r[7]);
        }
        __syncthreads();

        // out row t = ty, cols tx*4..+3
        ull av2[2] = {0ull, 0ull};
        ull ai2[2] = {0ull, 0ull};
        float gt = sG[ty];

        for (int i4 = 0; i4 <= ty; i4 += 4) {
            ull vv0[4], vv1[4];
#pragma unroll
            for (int ii = 0; ii < 4; ii++) {
                vv0[ii] = *(ull*)&sv[(i4 + ii) * 36 + tx * 4];
                vv1[ii] = *(ull*)&sv[(i4 + ii) * 36 + tx * 4 + 2];
            }
            float4 avv = *(float4*)&sA[ty * 68 + i4];
            ull s;
            s = bcast2(avv.x); fma2(av2[0], s, vv0[0]); fma2(av2[1], s, vv1[0]);
            s = bcast2(avv.y); fma2(av2[0], s, vv0[1]); fma2(av2[1], s, vv1[1]);
            s = bcast2(avv.z); fma2(av2[0], s, vv0[2]); fma2(av2[1], s, vv1[2]);
            s = bcast2(avv.w); fma2(av2[0], s, vv0[3]); fma2(av2[1], s, vv1[3]);
        }
        if (gt > -30.f) {
            for (int k4 = 0; k4 < DK_; k4 += 4) {
                ull s0[4], s1[4];
#pragma unroll
                for (int kk = 0; kk < 4; kk++) {
                    s0[kk] = *(ull*)&sS[(k4 + kk) * 36 + tx * 4];
                    s1[kk] = *(ull*)&sS[(k4 + kk) * 36 + tx * 4 + 2];
                }
                float4 qa = *(float4*)&sq[ty * 132 + k4];
                ull s;
                s = bcast2(qa.x); fma2(ai2[0], s, s0[0]); fma2(ai2[1], s, s1[0]);
                s = bcast2(qa.y); fma2(ai2[0], s, s0[1]); fma2(ai2[1], s, s1[1]);
                s = bcast2(qa.z); fma2(ai2[0], s, s0[2]); fma2(ai2[1], s, s1[2]);
                s = bcast2(qa.w); fma2(ai2[0], s, s0[3]); fma2(ai2[1], s, s1[3]);
            }
        }
        {
            ull e2 = bcast2(expf(gt));
            fma2(av2[0], e2, ai2[0]);
            fma2(av2[1], e2, ai2[1]);
            float* dst = g_o + (size_t)(b * T_ + t0 + ty) * VAL_DIM_ + h * DV_ + vs * DVS + tx * 4;
            *(ull*)dst       = av2[0];
            *(ull*)(dst + 2) = av2[1];
        }
        __syncthreads();

        // state update: rows ty*2, ty*2+1
        ull el2 = bcast2(expf(sG[63]));
        ull S0[2][2];
#pragma unroll
        for (int j = 0; j < 2; j++) {
            S0[j][0] = *(ull*)&sS[(ty * 2 + j) * 36 + tx * 4];
            S0[j][1] = *(ull*)&sS[(ty * 2 + j) * 36 + tx * 4 + 2];
            mul2(S0[j][0], el2); mul2(S0[j][1], el2);
        }
        for (int i = 0; i < LCH; i++) {
            float w = sW[i];
            if (w == 0.f) continue;
            ull v0 = *(ull*)&sv[i * 36 + tx * 4];
            ull v1 = *(ull*)&sv[i * 36 + tx * 4 + 2];
            float2 k0 = *(float2*)&sk[i * 132 + ty * 2];
            ull s;
            s = bcast2(w * k0.x); fma2(S0[0][0], s, v0); fma2(S0[0][1], s, v1);
            s = bcast2(w * k0.y); fma2(S0[1][0], s, v0); fma2(S0[1][1], s, v1);
        }
#pragma unroll
        for (int j = 0; j < 2; j++) {
            *(ull*)&sS[(ty * 2 + j) * 36 + tx * 4]     = S0[j][0];
            *(ull*)&sS[(ty * 2 + j) * 36 + tx * 4 + 2] = S0[j][1];
        }
    }
}

// ---------------- gated RMSNorm -> fp16, per-batch ----------------
__global__ void rmsnorm_kernel(const float* __restrict__ norm_w, int btBase)
{
    int bh = blockIdx.x;
    int bt = btBase + (bh >> 5), h = bh & 31;
    int tid = threadIdx.x;
    long idx = (long)bt * VAL_DIM_ + h * DV_ + tid;
    float o = g_o[idx];
    float z = g_z[idx];
    float val = o * (z / (1.f + expf(-z)));
    float s = val * val;
#pragma unroll
    for (int off = 16; off; off >>= 1) s += __shfl_xor_sync(0xffffffffu, s, off);
    __shared__ float red[4];
    int warp = tid >> 5, lane = tid & 31;
    if (lane == 0) red[warp] = s;
    __syncthreads();
    float tot = red[0] + red[1] + red[2] + red[3];
    float scale = rsqrtf(tot * (1.f / 128.f) + 1e-6f) * norm_w[tid];
    g_oh[idx] = __float2half_rn(val * scale);
}

// ---------------- launch: batch-pipelined, 3 streams, records before waits ----------------
extern "C" void kernel_launch(void* const* d_in, const int* in_sizes, int n_in,
                              void* d_out, int out_size)
{
    const float* x          = (const float*)d_in[0];
    const int*   input_pos  = (const int*)  d_in[1];
    const float* W_qkv      = (const float*)d_in[2];
    const float* W_z        = (const float*)d_in[3];
    const float* W_b        = (const float*)d_in[4];
    const float* W_a        = (const float*)d_in[5];
    const float* conv_w     = (const float*)d_in[6];
    const float* dt_bias    = (const float*)d_in[7];
    const float* A_log      = (const float*)d_in[8];
    const float* norm_w     = (const float*)d_in[9];
    const float* W_out      = (const float*)d_in[10];
    const float* conv_state = (const float*)d_in[11];
    const float* rstate     = (const float*)d_in[12];
    float* out = (float*)d_out;

    float *p_qkv, *p_z;
    __half *p_xh, *p_Wqh, *p_Wzh, *p_Woh, *p_oh;
    cudaGetSymbolAddress((void**)&p_qkv, g_qkv);
    cudaGetSymbolAddress((void**)&p_z,   g_z);
    cudaGetSymbolAddress((void**)&p_xh,  g_xh);
    cudaGetSymbolAddress((void**)&p_Wqh, g_Wqh);
    cudaGetSymbolAddress((void**)&p_Wzh, g_Wzh);
    cudaGetSymbolAddress((void**)&p_Woh, g_Woh);
    cudaGetSymbolAddress((void**)&p_oh,  g_oh);

    const int RECUR_SMEM = (64*132*2 + 64*36 + 64*68 + 128*36 + 64*3) * 4;   // 113408 B
    const int QK_SMEM    = (64*132*2) * 4;
    const int HG_SMEM    = 3 * 2 * HSTG * 2;   // 110592 B
    cudaFuncSetAttribute(recur_kernel, cudaFuncAttributeMaxDynamicSharedMemorySize, RECUR_SMEM);
    cudaFuncSetAttribute(qk_kernel,    cudaFuncAttributeMaxDynamicSharedMemorySize, QK_SMEM);
    cudaFuncSetAttribute(hgemm_nt,     cudaFuncAttributeMaxDynamicSharedMemorySize, HG_SMEM);

    static cudaStream_t sZ = nullptr, sBA = nullptr;
    static cudaEvent_t evRoot, evX, evQ0, evBA, evZ0, evZ1, evP0;
    if (!sZ) {
        cudaStreamCreateWithFlags(&sZ,  cudaStreamNonBlocking);
        cudaStreamCreateWithFlags(&sBA, cudaStreamNonBlocking);
        cudaEventCreateWithFlags(&evRoot, cudaEventDisableTiming);
        cudaEventCreateWithFlags(&evX,    cudaEventDisableTiming);
        cudaEventCreateWithFlags(&evQ0,   cudaEventDisableTiming);
        cudaEventCreateWithFlags(&evBA,   cudaEventDisableTiming);
        cudaEventCreateWithFlags(&evZ0,   cudaEventDisableTiming);
        cudaEventCreateWithFlags(&evZ1,   cudaEventDisableTiming);
        cudaEventCreateWithFlags(&evP0,   cudaEventDisableTiming);
    }

    // ---- fork ----
    cudaEventRecord(evRoot, 0);
    cudaStreamWaitEvent(sZ,  evRoot, 0);
    cudaStreamWaitEvent(sBA, evRoot, 0);

    // 1) main: cvt(x, Wq) -> qkv_b0 -> qkv_b1 (records evX, evQ0)
    cvt2<<<((BT_*C_/4 + CONV_DIM_*C_/4) + 255)/256, 256>>>(x, p_xh, BT_*C_/4, W_qkv, p_Wqh, CONV_DIM_*C_/4);
    cudaEventRecord(evX, 0);
    hgemm_nt<<<dim3(CONV_DIM_/128, T_/128), 256, HG_SMEM>>>(p_xh, p_Wqh, p_qkv, CONV_DIM_, C_, 0);
    cudaEventRecord(evQ0, 0);
    hgemm_nt<<<dim3(CONV_DIM_/128, T_/128), 256, HG_SMEM>>>(p_xh, p_Wqh, p_qkv, CONV_DIM_, C_, T_);

    // 2) sZ branch: cvt(Wz, Wo) -> z_b0 -> z_b1 (records evZ0, evZ1)
    cvt2<<<((VAL_DIM_*C_/4 + C_*VAL_DIM_/4) + 255)/256, 256, 0, sZ>>>(W_z, p_Wzh, VAL_DIM_*C_/4, W_out, p_Woh, C_*VAL_DIM_/4);
    cudaStreamWaitEvent(sZ, evX, 0);
    hgemm_nt<<<dim3(VAL_DIM_/128, T_/128), 256, HG_SMEM, sZ>>>(p_xh, p_Wzh, p_z, VAL_DIM_, C_, 0);
    cudaEventRecord(evZ0, sZ);
    hgemm_nt<<<dim3(VAL_DIM_/128, T_/128), 256, HG_SMEM, sZ>>>(p_xh, p_Wzh, p_z, VAL_DIM_, C_, T_);
    cudaEventRecord(evZ1, sZ);

    // 3) sBA branch: ba GEMM (+beta/g) -> evBA -> batch-0 pipeline -> evP0
    sgemm_ba_fused<<<dim3(1, BT_/128), 256, 0, sBA>>>(x, W_b, W_a, dt_bias, A_log);
    cudaEventRecord(evBA, sBA);
    cudaStreamWaitEvent(sBA, evQ0, 0);
    conv_kernel<<<T_/CTT, 256, 0, sBA>>>(conv_w, conv_state, input_pos, 0);
    qk_kernel<<<NHK_ * NCH, 256, QK_SMEM, sBA>>>(0);
    recur_kernel<<<NV_ * SPLITV, 512, RECUR_SMEM, sBA>>>(rstate, input_pos, 0);
    cudaStreamWaitEvent(sBA, evZ0, 0);
    rmsnorm_kernel<<<T_ * NV_, 128, 0, sBA>>>(norm_w, 0);
    hgemm_nt<<<dim3(C_/128, T_/128), 256, HG_SMEM, sBA>>>(p_oh, p_Woh, out, C_, VAL_DIM_, 0);
    cudaEventRecord(evP0, sBA);

    // 4) main: batch-1 chain (all waited events recorded above)
    conv_kernel<<<T_/CTT, 256>>>(conv_w, conv_state, input_pos, 1);
    qk_kernel<<<NHK_ * NCH, 256, QK_SMEM>>>(1);
    cudaStreamWaitEvent(0, evBA, 0);
    recur_kernel<<<NV_ * SPLITV, 512, RECUR_SMEM>>>(rstate, input_pos, 1);
    cudaStreamWaitEvent(0, evZ1, 0);
    rmsnorm_kernel<<<T_ * NV_, 128>>>(norm_w, T_);
    hgemm_nt<<<dim3(C_/128, T_/128), 256, HG_SMEM>>>(p_oh, p_Woh, out, C_, VAL_DIM_, T_);

    // 5) join batch-0 pipeline back to main
    cudaStreamWaitEvent(0, evP0, 0);
}

// round 16
// speedup vs baseline: 1.5886x; 1.5886x over previous
#include <cuda_runtime.h>
#include <cuda_fp16.h>
#include <math.h>
#include <stdint.h>

#define B_ 2
#define T_ 2048
#define C_ 2048
#define NV_ 32
#define NHK_ 16
#define DK_ 128
#define DV_ 128
#define KEY_DIM_ 2048
#define VAL_DIM_ 4096
#define CONV_DIM_ 8192
#define BT_ (B_*T_)
#define LCH 64
#define NCH (T_/LCH)
#define SPLITV 2
#define DVS (DV_/SPLITV)
#define CTT 8

typedef unsigned long long ull;

// ---------------- scratch (static device globals; no allocation) ----------------
__device__ float g_qkv [BT_*CONV_DIM_];
__device__ float g_z   [BT_*VAL_DIM_];
__device__ float g_q   [BT_*KEY_DIM_];
__device__ float g_k   [BT_*KEY_DIM_];
__device__ float g_v   [BT_*VAL_DIM_];
__device__ float g_beta[BT_*NV_];
__device__ float g_gg  [BT_*NV_];
__device__ float g_o   [BT_*VAL_DIM_];
__device__ float g_qk  [(size_t)B_*NHK_*NCH*LCH*LCH];

__device__ __half g_xh [BT_*C_];
__device__ __half g_Wqh[CONV_DIM_*C_];
__device__ __half g_Wzh[VAL_DIM_*C_];
__device__ __half g_Woh[C_*VAL_DIM_];
__device__ __half g_oh [BT_*VAL_DIM_];

// ---------------- helpers ----------------
__device__ __forceinline__ uint32_t smem_u32(const void* p) {
    uint32_t a;
    asm("{ .reg .u64 t; cvta.to.shared.u64 t, %1; cvt.u32.u64 %0, t; }" : "=r"(a) : "l"(p));
    return a;
}
__device__ __forceinline__ void ldsm_x4(uint32_t& r0, uint32_t& r1, uint32_t& r2, uint32_t& r3, uint32_t addr) {
    asm volatile("ldmatrix.sync.aligned.m8n8.x4.shared.b16 {%0,%1,%2,%3}, [%4];"
                 : "=r"(r0), "=r"(r1), "=r"(r2), "=r"(r3) : "r"(addr));
}
__device__ __forceinline__ void mma16816(float* c, uint32_t a0, uint32_t a1, uint32_t a2, uint32_t a3,
                                         uint32_t b0, uint32_t b1) {
    asm volatile("mma.sync.aligned.m16n8k16.row.col.f32.f16.f16.f32 "
                 "{%0,%1,%2,%3}, {%4,%5,%6,%7}, {%8,%9}, {%0,%1,%2,%3};"
                 : "+f"(c[0]), "+f"(c[1]), "+f"(c[2]), "+f"(c[3])
                 : "r"(a0), "r"(a1), "r"(a2), "r"(a3), "r"(b0), "r"(b1));
}
#define CP_ASYNC16(dst, src) asm volatile("cp.async.cg.shared.global [%0], [%1], 16;" :: "r"(dst), "l"(src))
#define CP_COMMIT()          asm volatile("cp.async.commit_group;" ::: "memory")
#define CP_WAIT1()           asm volatile("cp.async.wait_group 1;" ::: "memory")

// ---- packed fp32x2 ----
__device__ __forceinline__ ull bcast2(float s) {
    ull r; asm("mov.b64 %0, {%1, %1};" : "=l"(r) : "f"(s)); return r;
}
__device__ __forceinline__ void fma2(ull& a, ull s, ull b) {
    asm("fma.rn.f32x2 %0, %1, %2, %0;" : "+l"(a) : "l"(s), "l"(b));
}
__device__ __forceinline__ void mul2(ull& a, ull b) {
    asm("mul.rn.f32x2 %0, %0, %1;" : "+l"(a) : "l"(b));
}
__device__ __forceinline__ float2 unpack2(ull a) {
    float2 f; asm("mov.b64 {%0, %1}, %2;" : "=f"(f.x), "=f"(f.y) : "l"(a)); return f;
}

// ---------------- fp16 HGEMM: block 128x128, 8 warps (2Mx4N), warp 64x32 ----------------
// K-tile 64, 3-stage cp.async, one barrier per tile.
#define HSTG (128 * 72)
__global__ __launch_bounds__(256, 2)
void hgemm_nt(const __half* __restrict__ A, const __half* __restrict__ Bm,
              float* __restrict__ C, int N, int K, int rowBase)
{
    extern __shared__ __half hsm[];
    __half* AsP = hsm;
    __half* BsP = hsm + 3 * HSTG;

    int tid = threadIdx.x;
    int lane = tid & 31, wid = tid >> 5;
    int wm = wid & 1, wn = wid >> 1;
    int m0w = wm * 64, n0w = wn * 32;
    int row0 = rowBase + blockIdx.y * 128, col0 = blockIdx.x * 128;

    uint32_t aBase = smem_u32(AsP);
    uint32_t bBase = smem_u32(BsP);

    float acc[4][4][4];
#pragma unroll
    for (int i = 0; i < 4; i++)
#pragma unroll
        for (int j = 0; j < 4; j++)
#pragma unroll
            for (int e = 0; e < 4; e++) acc[i][j][e] = 0.f;

    const int NT = K >> 6;

    auto issue = [&](int kt, int s) {
        int k0 = kt << 6;
#pragma unroll
        for (int i = 0; i < 4; i++) {
            int f = tid + (i << 8);
            int r = f >> 3, c = (f & 7) << 3;
            CP_ASYNC16(aBase + ((s * HSTG + r * 72 + c) << 1),
                       A + (size_t)(row0 + r) * K + k0 + c);
        }
#pragma unroll
        for (int i = 0; i < 4; i++) {
            int f = tid + (i << 8);
            int r = f >> 3, c = (f & 7) << 3;
            CP_ASYNC16(bBase + ((s * HSTG + r * 72 + c) << 1),
                       Bm + (size_t)(col0 + r) * K + k0 + c);
        }
        CP_COMMIT();
    };

    issue(0, 0);
    issue(1, 1);

    for (int kt = 0; kt < NT; kt++) {
        CP_WAIT1();
        __syncthreads();
        if (kt + 2 < NT) issue(kt + 2, (kt + 2) % 3);
        int s = kt % 3;
#pragma unroll
        for (int kk = 0; kk < 64; kk += 16) {
            uint32_t a[4][4], b[4][2];
#pragma unroll
            for (int i = 0; i < 4; i++) {
                int r = m0w + i * 16 + (lane & 15);
                int c = kk + ((lane >> 4) << 3);
                ldsm_x4(a[i][0], a[i][1], a[i][2], a[i][3],
                        aBase + ((s * HSTG + r * 72 + c) << 1));
            }
#pragma unroll
            for (int j = 0; j < 2; j++) {
                int q = lane >> 3, rr = lane & 7;
                int r = n0w + j * 16 + ((q >> 1) << 3) + rr;
                int c = kk + ((q & 1) << 3);
                uint32_t t0, t1, t2, t3;
                ldsm_x4(t0, t1, t2, t3, bBase + ((s * HSTG + r * 72 + c) << 1));
                b[2*j][0] = t0; b[2*j][1] = t1; b[2*j+1][0] = t2; b[2*j+1][1] = t3;
            }
#pragma unroll
            for (int i = 0; i < 4; i++)
#pragma unroll
                for (int j = 0; j < 4; j++)
                    mma16816(acc[i][j], a[i][0], a[i][1], a[i][2], a[i][3], b[j][0], b[j][1]);
        }
    }

#pragma unroll
    for (int i = 0; i < 4; i++) {
        int r = row0 + m0w + i * 16 + (lane >> 2);
#pragma unroll
        for (int j = 0; j < 4; j++) {
            int c = col0 + n0w + j * 8 + ((lane & 3) << 1);
            *(float2*)&C[(size_t)r * N + c]       = make_float2(acc[i][j][0], acc[i][j][1]);
            *(float2*)&C[(size_t)(r + 8) * N + c] = make_float2(acc[i][j][2], acc[i][j][3]);
        }
    }
}

// ---------------- fp32 -> fp16 converters (two-tensor fused) ----------------
__global__ void cvt2(const float* __restrict__ s0, __half* __restrict__ d0, int n0,
                     const float* __restrict__ s1, __half* __restrict__ d1, int n1)
{
    int i = blockIdx.x * blockDim.x + threadIdx.x;
    const float* src; __half* dst; int off;
    if (i < n0)           { src = s0; dst = d0; off = i; }
    else if (i < n0 + n1) { src = s1; dst = d1; off = i - n0; }
    else return;
    float4 v = ((const float4*)src)[off];
    union { __half h[4]; uint2 u; } p;
    p.h[0] = __float2half_rn(v.x); p.h[1] = __float2half_rn(v.y);
    p.h[2] = __float2half_rn(v.z); p.h[3] = __float2half_rn(v.w);
    ((uint2*)dst)[off] = p.u;
}

// ---------------- fused fp32 GEMM for b|a + beta/g finalize ----------------
__global__ __launch_bounds__(256)
void sgemm_ba_fused(const float* __restrict__ A, const float* __restrict__ Wb,
                    const float* __restrict__ Wa, const float* __restrict__ dt_bias,
                    const float* __restrict__ A_log)
{
    __shared__ float As[16][128];
    __shared__ float Bs[16][64];
    int tid = threadIdx.x;
    int tx = tid & 15, ty = tid >> 4;
    int row0 = blockIdx.y * 128;

    float acc[8][4];
#pragma unroll
    for (int m = 0; m < 8; m++)
#pragma unroll
        for (int n = 0; n < 4; n++) acc[m][n] = 0.f;

    for (int kt = 0; kt < C_; kt += 16) {
#pragma unroll
        for (int i = 0; i < 2; i++) {
            int f = tid + i * 256;
            int r = f >> 2, c4 = (f & 3) << 2;
            float4 av = *(const float4*)(A + (size_t)(row0 + r) * C_ + kt + c4);
            As[c4][r] = av.x; As[c4+1][r] = av.y; As[c4+2][r] = av.z; As[c4+3][r] = av.w;
        }
        {
            int r = tid >> 2, c4 = (tid & 3) << 2;
            if (r < 64) {
                const float* src = (r < 32) ? (Wb + (size_t)r * C_) : (Wa + (size_t)(r - 32) * C_);
                float4 bv = *(const float4*)(src + kt + c4);
                Bs[c4][r] = bv.x; Bs[c4+1][r] = bv.y; Bs[c4+2][r] = bv.z; Bs[c4+3][r] = bv.w;
            }
        }
        __syncthreads();
#pragma unroll
        for (int k = 0; k < 16; k++) {
            float ra[8], rb[4];
            *(float4*)&ra[0] = *(float4*)&As[k][ty * 8];
            *(float4*)&ra[4] = *(float4*)&As[k][ty * 8 + 4];
            *(float4*)&rb[0] = *(float4*)&Bs[k][tx * 4];
#pragma unroll
            for (int m = 0; m < 8; m++)
#pragma unroll
                for (int n = 0; n < 4; n++) acc[m][n] += ra[m] * rb[n];
        }
        __syncthreads();
    }
#pragma unroll
    for (int m = 0; m < 8; m++) {
        int bt = row0 + ty * 8 + m;
#pragma unroll
        for (int n = 0; n < 4; n++) {
            int col = tx * 4 + n;
            float v = acc[m][n];
            if (col < 32) {
                g_beta[bt * NV_ + col] = 1.f / (1.f + expf(-v));
            } else {
                int h = col - 32;
                float a = v + dt_bias[h];
                float sp = (a > 20.f) ? a : log1pf(expf(a));
                g_gg[bt * NV_ + h] = -expf(A_log[h]) * sp;
            }
        }
    }
}

// ---------------- causal depthwise conv(K=4) + silu, per-batch (512 threads) ----------------
__global__ __launch_bounds__(512)
void conv_kernel(const float* __restrict__ conv_w,
                 const float* __restrict__ conv_state,
                 const int* __restrict__ input_pos, int bsel)
{
    int b = bsel;
    int t0 = blockIdx.x * CTT;
    int tid = threadIdx.x;
    float keep = (input_pos[0] == 0) ? 0.f : 1.f;

    for (int d = tid; d < CONV_DIM_; d += 512) {
        float4 w = *(const float4*)(conv_w + (size_t)d * 4);
        float xv[CTT + 3];
#pragma unroll
        for (int j = 0; j < CTT + 3; j++) {
            int tt = t0 - 3 + j;
            if (tt >= 0) xv[j] = g_qkv[(size_t)(b * T_ + tt) * CONV_DIM_ + d];
            else         xv[j] = keep * conv_state[((size_t)b * CONV_DIM_ + d) * 4 + (tt + 4)];
        }
#pragma unroll
        for (int to = 0; to < CTT; to++) {
            float acc = w.x * xv[to] + w.y * xv[to+1] + w.z * xv[to+2] + w.w * xv[to+3];
            float s = acc / (1.f + expf(-acc));
            size_t bt = (size_t)(b * T_ + t0 + to);
            if (d < 2048)      g_q[bt * KEY_DIM_ + d] = s;
            else if (d < 4096) g_k[bt * KEY_DIM_ + (d - 2048)] = s;
            else               g_v[bt * VAL_DIM_ + (d - 4096)] = s;
        }
    }
}

// normalize one 128-wide row held in smem (fp32)
__device__ __forceinline__ void norm_row_smem(float* row)
{
    float ss = 0.f;
#pragma unroll
    for (int c = 0; c < 32; c++) {
        float4 v = *(float4*)&row[c * 4];
        ss += v.x*v.x + v.y*v.y + v.z*v.z + v.w*v.w;
    }
    float inv = 1.f / fmaxf(sqrtf(ss), 1e-12f);
#pragma unroll
    for (int c = 0; c < 32; c++) {
        float4 v = *(float4*)&row[c * 4];
        v.x *= inv; v.y *= inv; v.z *= inv; v.w *= inv;
        *(float4*)&row[c * 4] = v;
    }
}

// ---------------- QK precompute: normalize q/k (write back) + raw scores ----------------
__global__ __launch_bounds__(256)
void qk_kernel(int bsel)
{
    extern __shared__ float qsm[];
    float* sq = qsm;
    float* sk = qsm + 64 * 132;

    int bidx = blockIdx.x;               // hk*NCH + ch
    int ch = bidx % NCH;
    int hk = bidx / NCH;
    int b  = bsel;
    int t0 = ch * LCH;
    int tid = threadIdx.x;
    int tx = tid & 15, ty = tid >> 4;

    for (int f = tid; f < 64 * 32; f += 256) {
        int r = f >> 5, c = (f & 31) * 4;
        *(float4*)&sq[r * 132 + c] = *(const float4*)(g_q + (size_t)(b * T_ + t0 + r) * KEY_DIM_ + hk * DK_ + c);
        *(float4*)&sk[r * 132 + c] = *(const float4*)(g_k + (size_t)(b * T_ + t0 + r) * KEY_DIM_ + hk * DK_ + c);
    }
    __syncthreads();
    if (tid < 128) {
        float* row = (tid < 64) ? (sq + tid * 132) : (sk + (tid - 64) * 132);
        norm_row_smem(row);
    }
    __syncthreads();
    // write normalized q/k back so recur skips normalization
    for (int f = tid; f < 64 * 32; f += 256) {
        int r = f >> 5, c = (f & 31) * 4;
        *(float4*)(g_q + (size_t)(b * T_ + t0 + r) * KEY_DIM_ + hk * DK_ + c) = *(float4*)&sq[r * 132 + c];
        *(float4*)(g_k + (size_t)(b * T_ + t0 + r) * KEY_DIM_ + hk * DK_ + c) = *(float4*)&sk[r * 132 + c];
    }

    ull acc2[4][4];
#pragma unroll
    for (int a = 0; a < 4; a++)
#pragma unroll
        for (int c = 0; c < 4; c++) acc2[a][c] = 0ull;

    if (tx * 4 <= ty * 4 + 3) {
        for (int k4 = 0; k4 < DK_; k4 += 4) {
            ull kb0[4], kb1[4];
#pragma unroll
            for (int c = 0; c < 4; c++) {
                kb0[c] = *(ull*)&sk[(tx * 4 + c) * 132 + k4];
                kb1[c] = *(ull*)&sk[(tx * 4 + c) * 132 + k4 + 2];
            }
#pragma unroll
            for (int a = 0; a < 4; a++) {
                ull qa0 = *(ull*)&sq[(ty * 4 + a) * 132 + k4];
                ull qa1 = *(ull*)&sq[(ty * 4 + a) * 132 + k4 + 2];
#pragma unroll
                for (int c = 0; c < 4; c++) {
                    fma2(acc2[a][c], qa0, kb0[c]);
                    fma2(acc2[a][c], qa1, kb1[c]);
                }
            }
        }
    }
    float* dst = g_qk + ((size_t)((b * NHK_ + hk) * NCH + ch)) * (LCH * LCH);
#pragma unroll
    for (int a = 0; a < 4; a++) {
        float r[4];
#pragma unroll
        for (int c = 0; c < 4; c++) {
            float2 p = unpack2(acc2[a][c]);
            r[c] = p.x + p.y;
        }
        *(float4*)&dst[(ty * 4 + a) * 64 + tx * 4] = make_float4(r[0], r[1], r[2], r[3]);
    }
}

// ---------------- recurrence (512 thr, f32x2), per-batch; q/k pre-normalized ----------------
__global__ __launch_bounds__(512)
void recur_kernel(const float* __restrict__ rstate, const int* __restrict__ input_pos, int bsel)
{
    extern __shared__ float sm[];
    float* sq = sm;
    float* sk = sq + 64 * 132;
    float* sv = sk + 64 * 132;
    float* sA = sv + 64 * 68;
    float* sS = sA + 64 * 68;
    float* sG = sS + 128 * 68;
    float* sB = sG + 64;
    float* sW = sB + 64;

    int bidx = blockIdx.x;               // vs + 2*h
    int vs = bidx & 1;
    int h  = (bidx >> 1) & (NV_ - 1);
    int b  = bsel;
    int hk = h >> 1;
    int tid = threadIdx.x;
    int tx = tid & 15, ty = tid >> 4;
    float keep = (input_pos[0] == 0) ? 0.f : 1.f;

#pragma unroll
    for (int j = 0; j < 4; j++) {
        int kk = ty * 4 + j;
        float4 v4 = *(const float4*)(rstate + (((size_t)(b * NV_ + h)) * DK_ + kk) * DV_ + vs * DVS + tx * 4);
        v4.x *= keep; v4.y *= keep; v4.z *= keep; v4.w *= keep;
        *(float4*)&sS[kk * 68 + tx * 4] = v4;
    }

    const float* qkBase = g_qk + ((size_t)(b * NHK_ + hk) * NCH) * (LCH * LCH);

    for (int ch = 0; ch < NCH; ch++) {
        int t0 = ch * LCH;
        __syncthreads();
        for (int f = tid; f < 64 * 32; f += 512) {
            int r = f >> 5, c = (f & 31) * 4;
            *(float4*)&sq[r * 132 + c] = *(const float4*)(g_q + (size_t)(b * T_ + t0 + r) * KEY_DIM_ + hk * DK_ + c);
            *(float4*)&sk[r * 132 + c] = *(const float4*)(g_k + (size_t)(b * T_ + t0 + r) * KEY_DIM_ + hk * DK_ + c);
        }
        for (int f = tid; f < 64 * 16; f += 512) {
            int r = f >> 4, c = (f & 15) * 4;
            *(float4*)&sv[r * 68 + c] = *(const float4*)(g_v + (size_t)(b * T_ + t0 + r) * VAL_DIM_ + h * DV_ + vs * DVS + c);
        }
        if (tid < 64) {
            sB[tid] = g_beta[(b * T_ + t0 + tid) * NV_ + h];
            sG[tid] = g_gg  [(b * T_ + t0 + tid) * NV_ + h];
        }
        __syncthreads();
        if (tid == 0) {
            float run = 0.f;
            for (int i = 0; i < LCH; i++) { run += sG[i]; sG[i] = run; }
        }
        __syncthreads();
        if (tid < 64) {
            float df = sG[63] - sG[tid];
            sW[tid] = (df > -30.f) ? expf(df) * sB[tid] : 0.f;
        }

        {
            const float* qkT = qkBase + (size_t)ch * (LCH * LCH);
            int f0 = tid * 8;
            int t = f0 >> 6, i0 = f0 & 63;
            float gt = sG[t];
            float4 qa = *(const float4*)(qkT + t * 64 + i0);
            float4 qb = *(const float4*)(qkT + t * 64 + i0 + 4);
            float r[8] = {qa.x, qa.y, qa.z, qa.w, qb.x, qb.y, qb.z, qb.w};
#pragma unroll
            for (int j = 0; j < 8; j++) {
                int i = i0 + j;
                float d = gt - sG[i];
                r[j] = (i <= t && d > -30.f) ? r[j] * expf(d) * sB[i] : 0.f;
            }
            *(float4*)&sA[t * 68 + i0]     = make_float4(r[0], r[1], r[2], r[3]);
            *(float4*)&sA[t * 68 + i0 + 4] = make_float4(r[4], r[5], r[6], r[7]);
        }
        __syncthreads();

        int r0 = ty * 2, r1 = r0 + 1;
        ull av2[2][2] = {{0ull,0ull},{0ull,0ull}};
        ull ai2[2][2] = {{0ull,0ull},{0ull,0ull}};
        float gr0 = sG[r0];

        for (int i4 = 0; i4 <= r1; i4 += 4) {
            ull vv0[4], vv1[4];
#pragma unroll
            for (int ii = 0; ii < 4; ii++) {
                vv0[ii] = *(ull*)&sv[(i4 + ii) * 68 + tx * 4];
                vv1[ii] = *(ull*)&sv[(i4 + ii) * 68 + tx * 4 + 2];
            }
#pragma unroll
            for (int a = 0; a < 2; a++) {
                float4 avv = *(float4*)&sA[(r0 + a) * 68 + i4];
                ull s;
                s = bcast2(avv.x); fma2(av2[a][0], s, vv0[0]); fma2(av2[a][1], s, vv1[0]);
                s = bcast2(avv.y); fma2(av2[a][0], s, vv0[1]); fma2(av2[a][1], s, vv1[1]);
                s = bcast2(avv.z); fma2(av2[a][0], s, vv0[2]); fma2(av2[a][1], s, vv1[2]);
                s = bcast2(avv.w); fma2(av2[a][0], s, vv0[3]); fma2(av2[a][1], s, vv1[3]);
            }
        }
        if (gr0 > -30.f) {
            for (int k4 = 0; k4 < DK_; k4 += 4) {
                ull s0[4], s1[4];
#pragma unroll
                for (int kk = 0; kk < 4; kk++) {
                    s0[kk] = *(ull*)&sS[(k4 + kk) * 68 + tx * 4];
                    s1[kk] = *(ull*)&sS[(k4 + kk) * 68 + tx * 4 + 2];
                }
#pragma unroll
                for (int a = 0; a < 2; a++) {
                    float4 qa = *(float4*)&sq[(r0 + a) * 132 + k4];
                    ull s;
                    s = bcast2(qa.x); fma2(ai2[a][0], s, s0[0]); fma2(ai2[a][1], s, s1[0]);
                    s = bcast2(qa.y); fma2(ai2[a][0], s, s0[1]); fma2(ai2[a][1], s, s1[1]);
                    s = bcast2(qa.z); fma2(ai2[a][0], s, s0[2]); fma2(ai2[a][1], s, s1[2]);
                    s = bcast2(qa.w); fma2(ai2[a][0], s, s0[3]); fma2(ai2[a][1], s, s1[3]);
                }
            }
        }
#pragma unroll
        for (int a = 0; a < 2; a++) {
            int t = r0 + a;
            ull e2 = bcast2(expf(sG[t]));
            fma2(av2[a][0], e2, ai2[a][0]);
            fma2(av2[a][1], e2, ai2[a][1]);
            float* dst = g_o + (size_t)(b * T_ + t0 + t) * VAL_DIM_ + h * DV_ + vs * DVS + tx * 4;
            *(ull*)dst       = av2[a][0];
            *(ull*)(dst + 2) = av2[a][1];
        }
        __syncthreads();

        ull el2 = bcast2(expf(sG[63]));
        ull S0[4], S1[4];
#pragma unroll
        for (int j = 0; j < 4; j++) {
            S0[j] = *(ull*)&sS[(ty * 4 + j) * 68 + tx * 4];
            S1[j] = *(ull*)&sS[(ty * 4 + j) * 68 + tx * 4 + 2];
            mul2(S0[j], el2); mul2(S1[j], el2);
        }
        for (int i = 0; i < LCH; i++) {
            float w = sW[i];
            if (w == 0.f) continue;
            ull v0 = *(ull*)&sv[i * 68 + tx * 4];
            ull v1 = *(ull*)&sv[i * 68 + tx * 4 + 2];
            float4 k0 = *(float4*)&sk[i * 132 + ty * 4];
            ull s;
            s = bcast2(w * k0.x); fma2(S0[0], s, v0); fma2(S1[0], s, v1);
            s = bcast2(w * k0.y); fma2(S0[1], s, v0); fma2(S1[1], s, v1);
            s = bcast2(w * k0.z); fma2(S0[2], s, v0); fma2(S1[2], s, v1);
            s = bcast2(w * k0.w); fma2(S0[3], s, v0); fma2(S1[3], s, v1);
        }
#pragma unroll
        for (int j = 0; j < 4; j++) {
            *(ull*)&sS[(ty * 4 + j) * 68 + tx * 4]     = S0[j];
            *(ull*)&sS[(ty * 4 + j) * 68 + tx * 4 + 2] = S1[j];
        }
    }
}

// ---------------- gated RMSNorm -> fp16, per-batch ----------------
__global__ void rmsnorm_kernel(const float* __restrict__ norm_w, int btBase)
{
    int bh = blockIdx.x;
    int bt = btBase + (bh >> 5), h = bh & 31;
    int tid = threadIdx.x;
    long idx = (long)bt * VAL_DIM_ + h * DV_ + tid;
    float o = g_o[idx];
    float z = g_z[idx];
    float val = o * (z / (1.f + expf(-z)));
    float s = val * val;
#pragma unroll
    for (int off = 16; off; off >>= 1) s += __shfl_xor_sync(0xffffffffu, s, off);
    __shared__ float red[4];
    int warp = tid >> 5, lane = tid & 31;
    if (lane == 0) red[warp] = s;
    __syncthreads();
    float tot = red[0] + red[1] + red[2] + red[3];
    float scale = rsqrtf(tot * (1.f / 128.f) + 1e-6f) * norm_w[tid];
    g_oh[idx] = __float2half_rn(val * scale);
}

// ---------------- launch: batch-pipelined, 3 streams, records before waits ----------------
extern "C" void kernel_launch(void* const* d_in, const int* in_sizes, int n_in,
                              void* d_out, int out_size)
{
    const float* x          = (const float*)d_in[0];
    const int*   input_pos  = (const int*)  d_in[1];
    const float* W_qkv      = (const float*)d_in[2];
    const float* W_z        = (const float*)d_in[3];
    const float* W_b        = (const float*)d_in[4];
    const float* W_a        = (const float*)d_in[5];
    const float* conv_w     = (const float*)d_in[6];
    const float* dt_bias    = (const float*)d_in[7];
    const float* A_log      = (const float*)d_in[8];
    const float* norm_w     = (const float*)d_in[9];
    const float* W_out      = (const float*)d_in[10];
    const float* conv_state = (const float*)d_in[11];
    const float* rstate     = (const float*)d_in[12];
    float* out = (float*)d_out;

    float *p_qkv, *p_z;
    __half *p_xh, *p_Wqh, *p_Wzh, *p_Woh, *p_oh;
    cudaGetSymbolAddress((void**)&p_qkv, g_qkv);
    cudaGetSymbolAddress((void**)&p_z,   g_z);
    cudaGetSymbolAddress((void**)&p_xh,  g_xh);
    cudaGetSymbolAddress((void**)&p_Wqh, g_Wqh);
    cudaGetSymbolAddress((void**)&p_Wzh, g_Wzh);
    cudaGetSymbolAddress((void**)&p_Woh, g_Woh);
    cudaGetSymbolAddress((void**)&p_oh,  g_oh);

    const int RECUR_SMEM = (64*132*2 + 64*68*2 + 128*68 + 64*3) * 4;
    const int QK_SMEM    = (64*132*2) * 4;
    const int HG_SMEM    = 3 * 2 * HSTG * 2;   // 110592 B
    cudaFuncSetAttribute(recur_kernel, cudaFuncAttributeMaxDynamicSharedMemorySize, RECUR_SMEM);
    cudaFuncSetAttribute(qk_kernel,    cudaFuncAttributeMaxDynamicSharedMemorySize, QK_SMEM);
    cudaFuncSetAttribute(hgemm_nt,     cudaFuncAttributeMaxDynamicSharedMemorySize, HG_SMEM);

    static cudaStream_t sZ = nullptr, sBA = nullptr;
    static cudaEvent_t evRoot, evX, evQ0, evBA, evZ0, evZ1, evP0;
    if (!sZ) {
        cudaStreamCreateWithFlags(&sZ,  cudaStreamNonBlocking);
        cudaStreamCreateWithFlags(&sBA, cudaStreamNonBlocking);
        cudaEventCreateWithFlags(&evRoot, cudaEventDisableTiming);
        cudaEventCreateWithFlags(&evX,    cudaEventDisableTiming);
        cudaEventCreateWithFlags(&evQ0,   cudaEventDisableTiming);
        cudaEventCreateWithFlags(&evBA,   cudaEventDisableTiming);
        cudaEventCreateWithFlags(&evZ0,   cudaEventDisableTiming);
        cudaEventCreateWithFlags(&evZ1,   cudaEventDisableTiming);
        cudaEventCreateWithFlags(&evP0,   cudaEventDisableTiming);
    }

    // ---- fork ----
    cudaEventRecord(evRoot, 0);
    cudaStreamWaitEvent(sZ,  evRoot, 0);
    cudaStreamWaitEvent(sBA, evRoot, 0);

    // 1) main: cvt(x, Wq) -> qkv_b0 -> qkv_b1 (records evX, evQ0)
    cvt2<<<((BT_*C_/4 + CONV_DIM_*C_/4) + 255)/256, 256>>>(x, p_xh, BT_*C_/4, W_qkv, p_Wqh, CONV_DIM_*C_/4);
    cudaEventRecord(evX, 0);
    hgemm_nt<<<dim3(CONV_DIM_/128, T_/128), 256, HG_SMEM>>>(p_xh, p_Wqh, p_qkv, CONV_DIM_, C_, 0);
    cudaEventRecord(evQ0, 0);
    hgemm_nt<<<dim3(CONV_DIM_/128, T_/128), 256, HG_SMEM>>>(p_xh, p_Wqh, p_qkv, CONV_DIM_, C_, T_);

    // 2) sZ branch: cvt(Wz, Wo) -> z_b0 -> z_b1 (records evZ0, evZ1)
    cvt2<<<((VAL_DIM_*C_/4 + C_*VAL_DIM_/4) + 255)/256, 256, 0, sZ>>>(W_z, p_Wzh, VAL_DIM_*C_/4, W_out, p_Woh, C_*VAL_DIM_/4);
    cudaStreamWaitEvent(sZ, evX, 0);
    hgemm_nt<<<dim3(VAL_DIM_/128, T_/128), 256, HG_SMEM, sZ>>>(p_xh, p_Wzh, p_z, VAL_DIM_, C_, 0);
    cudaEventRecord(evZ0, sZ);
    hgemm_nt<<<dim3(VAL_DIM_/128, T_/128), 256, HG_SMEM, sZ>>>(p_xh, p_Wzh, p_z, VAL_DIM_, C_, T_);
    cudaEventRecord(evZ1, sZ);

    // 3) sBA branch: ba GEMM (+beta/g) -> evBA -> batch-0 pipeline -> evP0
    sgemm_ba_fused<<<dim3(1, BT_/128), 256, 0, sBA>>>(x, W_b, W_a, dt_bias, A_log);
    cudaEventRecord(evBA, sBA);
    cudaStreamWaitEvent(sBA, evQ0, 0);
    conv_kernel<<<T_/CTT, 512, 0, sBA>>>(conv_w, conv_state, input_pos, 0);
    qk_kernel<<<NHK_ * NCH, 256, QK_SMEM, sBA>>>(0);
    recur_kernel<<<NV_ * SPLITV, 512, RECUR_SMEM, sBA>>>(rstate, input_pos, 0);
    cudaStreamWaitEvent(sBA, evZ0, 0);
    rmsnorm_kernel<<<T_ * NV_, 128, 0, sBA>>>(norm_w, 0);
    hgemm_nt<<<dim3(C_/128, T_/128), 256, HG_SMEM, sBA>>>(p_oh, p_Woh, out, C_, VAL_DIM_, 0);
    cudaEventRecord(evP0, sBA);

    // 4) main: batch-1 chain (all waited events recorded above)
    conv_kernel<<<T_/CTT, 512>>>(conv_w, conv_state, input_pos, 1);
    qk_kernel<<<NHK_ * NCH, 256, QK_SMEM>>>(1);
    cudaStreamWaitEvent(0, evBA, 0);
    recur_kernel<<<NV_ * SPLITV, 512, RECUR_SMEM>>>(rstate, input_pos, 1);
    cudaStreamWaitEvent(0, evZ1, 0);
    rmsnorm_kernel<<<T_ * NV_, 128>>>(norm_w, T_);
    hgemm_nt<<<dim3(C_/128, T_/128), 256, HG_SMEM>>>(p_oh, p_Woh, out, C_, VAL_DIM_, T_);

    // 5) join batch-0 pipeline back to main
    cudaStreamWaitEvent(0, evP0, 0);
}

// round 17
// speedup vs baseline: 1.6479x; 1.0373x over previous
#include <cuda_runtime.h>
#include <cuda_fp16.h>
#include <math.h>
#include <stdint.h>

#define B_ 2
#define T_ 2048
#define C_ 2048
#define NV_ 32
#define NHK_ 16
#define DK_ 128
#define DV_ 128
#define KEY_DIM_ 2048
#define VAL_DIM_ 4096
#define CONV_DIM_ 8192
#define BT_ (B_*T_)
#define LCH 64
#define NCH (T_/LCH)
#define SPLITV 4
#define DVS (DV_/SPLITV)
#define CTT 8

typedef unsigned long long ull;

// ---------------- scratch (static device globals; no allocation) ----------------
__device__ float g_qkv [BT_*CONV_DIM_];
__device__ float g_z   [BT_*VAL_DIM_];
__device__ float g_q   [BT_*KEY_DIM_];
__device__ float g_k   [BT_*KEY_DIM_];
__device__ float g_v   [BT_*VAL_DIM_];
__device__ float g_beta[BT_*NV_];
__device__ float g_gg  [BT_*NV_];
__device__ float g_o   [BT_*VAL_DIM_];
__device__ float g_qk  [(size_t)B_*NHK_*NCH*LCH*LCH];

__device__ __half g_xh [BT_*C_];
__device__ __half g_Wqh[CONV_DIM_*C_];
__device__ __half g_Wzh[VAL_DIM_*C_];
__device__ __half g_Woh[C_*VAL_DIM_];
__device__ __half g_oh [BT_*VAL_DIM_];

// ---------------- helpers ----------------
__device__ __forceinline__ uint32_t smem_u32(const void* p) {
    uint32_t a;
    asm("{ .reg .u64 t; cvta.to.shared.u64 t, %1; cvt.u32.u64 %0, t; }" : "=r"(a) : "l"(p));
    return a;
}
__device__ __forceinline__ void ldsm_x4(uint32_t& r0, uint32_t& r1, uint32_t& r2, uint32_t& r3, uint32_t addr) {
    asm volatile("ldmatrix.sync.aligned.m8n8.x4.shared.b16 {%0,%1,%2,%3}, [%4];"
                 : "=r"(r0), "=r"(r1), "=r"(r2), "=r"(r3) : "r"(addr));
}
__device__ __forceinline__ void mma16816(float* c, uint32_t a0, uint32_t a1, uint32_t a2, uint32_t a3,
                                         uint32_t b0, uint32_t b1) {
    asm volatile("mma.sync.aligned.m16n8k16.row.col.f32.f16.f16.f32 "
                 "{%0,%1,%2,%3}, {%4,%5,%6,%7}, {%8,%9}, {%0,%1,%2,%3};"
                 : "+f"(c[0]), "+f"(c[1]), "+f"(c[2]), "+f"(c[3])
                 : "r"(a0), "r"(a1), "r"(a2), "r"(a3), "r"(b0), "r"(b1));
}
#define CP_ASYNC16(dst, src) asm volatile("cp.async.cg.shared.global [%0], [%1], 16;" :: "r"(dst), "l"(src))
#define CP_COMMIT()          asm volatile("cp.async.commit_group;" ::: "memory")
#define CP_WAIT1()           asm volatile("cp.async.wait_group 1;" ::: "memory")

// ---- packed fp32x2 ----
__device__ __forceinline__ ull bcast2(float s) {
    ull r; asm("mov.b64 %0, {%1, %1};" : "=l"(r) : "f"(s)); return r;
}
__device__ __forceinline__ void fma2(ull& a, ull s, ull b) {
    asm("fma.rn.f32x2 %0, %1, %2, %0;" : "+l"(a) : "l"(s), "l"(b));
}
__device__ __forceinline__ void mul2(ull& a, ull b) {
    asm("mul.rn.f32x2 %0, %0, %1;" : "+l"(a) : "l"(b));
}
__device__ __forceinline__ float2 unpack2(ull a) {
    float2 f; asm("mov.b64 {%0, %1}, %2;" : "=f"(f.x), "=f"(f.y) : "l"(a)); return f;
}

// ---------------- fp16 HGEMM: block 128x128, 8 warps (2Mx4N), warp 64x32 ----------------
// K-tile 64, 3-stage cp.async, one barrier per tile.
#define HSTG (128 * 72)
__global__ __launch_bounds__(256, 2)
void hgemm_nt(const __half* __restrict__ A, const __half* __restrict__ Bm,
              float* __restrict__ C, int N, int K, int rowBase)
{
    extern __shared__ __half hsm[];
    __half* AsP = hsm;
    __half* BsP = hsm + 3 * HSTG;

    int tid = threadIdx.x;
    int lane = tid & 31, wid = tid >> 5;
    int wm = wid & 1, wn = wid >> 1;
    int m0w = wm * 64, n0w = wn * 32;
    int row0 = rowBase + blockIdx.y * 128, col0 = blockIdx.x * 128;

    uint32_t aBase = smem_u32(AsP);
    uint32_t bBase = smem_u32(BsP);

    float acc[4][4][4];
#pragma unroll
    for (int i = 0; i < 4; i++)
#pragma unroll
        for (int j = 0; j < 4; j++)
#pragma unroll
            for (int e = 0; e < 4; e++) acc[i][j][e] = 0.f;

    const int NT = K >> 6;

    auto issue = [&](int kt, int s) {
        int k0 = kt << 6;
#pragma unroll
        for (int i = 0; i < 4; i++) {
            int f = tid + (i << 8);
            int r = f >> 3, c = (f & 7) << 3;
            CP_ASYNC16(aBase + ((s * HSTG + r * 72 + c) << 1),
                       A + (size_t)(row0 + r) * K + k0 + c);
        }
#pragma unroll
        for (int i = 0; i < 4; i++) {
            int f = tid + (i << 8);
            int r = f >> 3, c = (f & 7) << 3;
            CP_ASYNC16(bBase + ((s * HSTG + r * 72 + c) << 1),
                       Bm + (size_t)(col0 + r) * K + k0 + c);
        }
        CP_COMMIT();
    };

    issue(0, 0);
    issue(1, 1);

    for (int kt = 0; kt < NT; kt++) {
        CP_WAIT1();
        __syncthreads();
        if (kt + 2 < NT) issue(kt + 2, (kt + 2) % 3);
        int s = kt % 3;
#pragma unroll
        for (int kk = 0; kk < 64; kk += 16) {
            uint32_t a[4][4], b[4][2];
#pragma unroll
            for (int i = 0; i < 4; i++) {
                int r = m0w + i * 16 + (lane & 15);
                int c = kk + ((lane >> 4) << 3);
                ldsm_x4(a[i][0], a[i][1], a[i][2], a[i][3],
                        aBase + ((s * HSTG + r * 72 + c) << 1));
            }
#pragma unroll
            for (int j = 0; j < 2; j++) {
                int q = lane >> 3, rr = lane & 7;
                int r = n0w + j * 16 + ((q >> 1) << 3) + rr;
                int c = kk + ((q & 1) << 3);
                uint32_t t0, t1, t2, t3;
                ldsm_x4(t0, t1, t2, t3, bBase + ((s * HSTG + r * 72 + c) << 1));
                b[2*j][0] = t0; b[2*j][1] = t1; b[2*j+1][0] = t2; b[2*j+1][1] = t3;
            }
#pragma unroll
            for (int i = 0; i < 4; i++)
#pragma unroll
                for (int j = 0; j < 4; j++)
                    mma16816(acc[i][j], a[i][0], a[i][1], a[i][2], a[i][3], b[j][0], b[j][1]);
        }
    }

#pragma unroll
    for (int i = 0; i < 4; i++) {
        int r = row0 + m0w + i * 16 + (lane >> 2);
#pragma unroll
        for (int j = 0; j < 4; j++) {
            int c = col0 + n0w + j * 8 + ((lane & 3) << 1);
            *(float2*)&C[(size_t)r * N + c]       = make_float2(acc[i][j][0], acc[i][j][1]);
            *(float2*)&C[(size_t)(r + 8) * N + c] = make_float2(acc[i][j][2], acc[i][j][3]);
        }
    }
}

// ---------------- fp32 -> fp16 converters (two-tensor fused) ----------------
__global__ void cvt2(const float* __restrict__ s0, __half* __restrict__ d0, int n0,
                     const float* __restrict__ s1, __half* __restrict__ d1, int n1)
{
    int i = blockIdx.x * blockDim.x + threadIdx.x;
    const float* src; __half* dst; int off;
    if (i < n0)           { src = s0; dst = d0; off = i; }
    else if (i < n0 + n1) { src = s1; dst = d1; off = i - n0; }
    else return;
    float4 v = ((const float4*)src)[off];
    union { __half h[4]; uint2 u; } p;
    p.h[0] = __float2half_rn(v.x); p.h[1] = __float2half_rn(v.y);
    p.h[2] = __float2half_rn(v.z); p.h[3] = __float2half_rn(v.w);
    ((uint2*)dst)[off] = p.u;
}

// ---------------- fused fp32 GEMM for b|a + beta/g finalize ----------------
__global__ __launch_bounds__(256)
void sgemm_ba_fused(const float* __restrict__ A, const float* __restrict__ Wb,
                    const float* __restrict__ Wa, const float* __restrict__ dt_bias,
                    const float* __restrict__ A_log)
{
    __shared__ float As[16][128];
    __shared__ float Bs[16][64];
    int tid = threadIdx.x;
    int tx = tid & 15, ty = tid >> 4;
    int row0 = blockIdx.y * 128;

    float acc[8][4];
#pragma unroll
    for (int m = 0; m < 8; m++)
#pragma unroll
        for (int n = 0; n < 4; n++) acc[m][n] = 0.f;

    for (int kt = 0; kt < C_; kt += 16) {
#pragma unroll
        for (int i = 0; i < 2; i++) {
            int f = tid + i * 256;
            int r = f >> 2, c4 = (f & 3) << 2;
            float4 av = *(const float4*)(A + (size_t)(row0 + r) * C_ + kt + c4);
            As[c4][r] = av.x; As[c4+1][r] = av.y; As[c4+2][r] = av.z; As[c4+3][r] = av.w;
        }
        {
            int r = tid >> 2, c4 = (tid & 3) << 2;
            if (r < 64) {
                const float* src = (r < 32) ? (Wb + (size_t)r * C_) : (Wa + (size_t)(r - 32) * C_);
                float4 bv = *(const float4*)(src + kt + c4);
                Bs[c4][r] = bv.x; Bs[c4+1][r] = bv.y; Bs[c4+2][r] = bv.z; Bs[c4+3][r] = bv.w;
            }
        }
        __syncthreads();
#pragma unroll
        for (int k = 0; k < 16; k++) {
            float ra[8], rb[4];
            *(float4*)&ra[0] = *(float4*)&As[k][ty * 8];
            *(float4*)&ra[4] = *(float4*)&As[k][ty * 8 + 4];
            *(float4*)&rb[0] = *(float4*)&Bs[k][tx * 4];
#pragma unroll
            for (int m = 0; m < 8; m++)
#pragma unroll
                for (int n = 0; n < 4; n++) acc[m][n] += ra[m] * rb[n];
        }
        __syncthreads();
    }
#pragma unroll
    for (int m = 0; m < 8; m++) {
        int bt = row0 + ty * 8 + m;
#pragma unroll
        for (int n = 0; n < 4; n++) {
            int col = tx * 4 + n;
            float v = acc[m][n];
            if (col < 32) {
                g_beta[bt * NV_ + col] = 1.f / (1.f + expf(-v));
            } else {
                int h = col - 32;
                float a = v + dt_bias[h];
                float sp = (a > 20.f) ? a : log1pf(expf(a));
                g_gg[bt * NV_ + h] = -expf(A_log[h]) * sp;
            }
        }
    }
}

// ---------------- causal depthwise conv(K=4) + silu, per-batch (512 threads) ----------------
__global__ __launch_bounds__(512)
void conv_kernel(const float* __restrict__ conv_w,
                 const float* __restrict__ conv_state,
                 const int* __restrict__ input_pos, int bsel)
{
    int b = bsel;
    int t0 = blockIdx.x * CTT;
    int tid = threadIdx.x;
    float keep = (input_pos[0] == 0) ? 0.f : 1.f;

    for (int d = tid; d < CONV_DIM_; d += 512) {
        float4 w = *(const float4*)(conv_w + (size_t)d * 4);
        float xv[CTT + 3];
#pragma unroll
        for (int j = 0; j < CTT + 3; j++) {
            int tt = t0 - 3 + j;
            if (tt >= 0) xv[j] = g_qkv[(size_t)(b * T_ + tt) * CONV_DIM_ + d];
            else         xv[j] = keep * conv_state[((size_t)b * CONV_DIM_ + d) * 4 + (tt + 4)];
        }
#pragma unroll
        for (int to = 0; to < CTT; to++) {
            float acc = w.x * xv[to] + w.y * xv[to+1] + w.z * xv[to+2] + w.w * xv[to+3];
            float s = acc / (1.f + expf(-acc));
            size_t bt = (size_t)(b * T_ + t0 + to);
            if (d < 2048)      g_q[bt * KEY_DIM_ + d] = s;
            else if (d < 4096) g_k[bt * KEY_DIM_ + (d - 2048)] = s;
            else               g_v[bt * VAL_DIM_ + (d - 4096)] = s;
        }
    }
}

// normalize one 128-wide row held in smem (fp32)
__device__ __forceinline__ void norm_row_smem(float* row)
{
    float ss = 0.f;
#pragma unroll
    for (int c = 0; c < 32; c++) {
        float4 v = *(float4*)&row[c * 4];
        ss += v.x*v.x + v.y*v.y + v.z*v.z + v.w*v.w;
    }
    float inv = 1.f / fmaxf(sqrtf(ss), 1e-12f);
#pragma unroll
    for (int c = 0; c < 32; c++) {
        float4 v = *(float4*)&row[c * 4];
        v.x *= inv; v.y *= inv; v.z *= inv; v.w *= inv;
        *(float4*)&row[c * 4] = v;
    }
}

// ---------------- QK precompute: normalize q/k (write back) + raw scores ----------------
__global__ __launch_bounds__(256)
void qk_kernel(int bsel)
{
    extern __shared__ float qsm[];
    float* sq = qsm;
    float* sk = qsm + 64 * 132;

    int bidx = blockIdx.x;               // hk*NCH + ch
    int ch = bidx % NCH;
    int hk = bidx / NCH;
    int b  = bsel;
    int t0 = ch * LCH;
    int tid = threadIdx.x;
    int tx = tid & 15, ty = tid >> 4;

    for (int f = tid; f < 64 * 32; f += 256) {
        int r = f >> 5, c = (f & 31) * 4;
        *(float4*)&sq[r * 132 + c] = *(const float4*)(g_q + (size_t)(b * T_ + t0 + r) * KEY_DIM_ + hk * DK_ + c);
        *(float4*)&sk[r * 132 + c] = *(const float4*)(g_k + (size_t)(b * T_ + t0 + r) * KEY_DIM_ + hk * DK_ + c);
    }
    __syncthreads();
    if (tid < 128) {
        float* row = (tid < 64) ? (sq + tid * 132) : (sk + (tid - 64) * 132);
        norm_row_smem(row);
    }
    __syncthreads();
    // write normalized q/k back so recur skips normalization
    for (int f = tid; f < 64 * 32; f += 256) {
        int r = f >> 5, c = (f & 31) * 4;
        *(float4*)(g_q + (size_t)(b * T_ + t0 + r) * KEY_DIM_ + hk * DK_ + c) = *(float4*)&sq[r * 132 + c];
        *(float4*)(g_k + (size_t)(b * T_ + t0 + r) * KEY_DIM_ + hk * DK_ + c) = *(float4*)&sk[r * 132 + c];
    }

    ull acc2[4][4];
#pragma unroll
    for (int a = 0; a < 4; a++)
#pragma unroll
        for (int c = 0; c < 4; c++) acc2[a][c] = 0ull;

    if (tx * 4 <= ty * 4 + 3) {
        for (int k4 = 0; k4 < DK_; k4 += 4) {
            ull kb0[4], kb1[4];
#pragma unroll
            for (int c = 0; c < 4; c++) {
                kb0[c] = *(ull*)&sk[(tx * 4 + c) * 132 + k4];
                kb1[c] = *(ull*)&sk[(tx * 4 + c) * 132 + k4 + 2];
            }
#pragma unroll
            for (int a = 0; a < 4; a++) {
                ull qa0 = *(ull*)&sq[(ty * 4 + a) * 132 + k4];
                ull qa1 = *(ull*)&sq[(ty * 4 + a) * 132 + k4 + 2];
#pragma unroll
                for (int c = 0; c < 4; c++) {
                    fma2(acc2[a][c], qa0, kb0[c]);
                    fma2(acc2[a][c], qa1, kb1[c]);
                }
            }
        }
    }
    float* dst = g_qk + ((size_t)((b * NHK_ + hk) * NCH + ch)) * (LCH * LCH);
#pragma unroll
    for (int a = 0; a < 4; a++) {
        float r[4];
#pragma unroll
        for (int c = 0; c < 4; c++) {
            float2 p = unpack2(acc2[a][c]);
            r[c] = p.x + p.y;
        }
        *(float4*)&dst[(ty * 4 + a) * 64 + tx * 4] = make_float4(r[0], r[1], r[2], r[3]);
    }
}

// ---------------- recurrence: SPLITV=4, 256 threads, 2 out rows/thread (f32x2) ----------------
// tx = tid&7 (8 col groups x 4 = 32 cols), ty = tid>>3 (0..31): out rows ty*2..+1, state rows ty*4..+3.
__global__ __launch_bounds__(256)
void recur_kernel(const float* __restrict__ rstate, const int* __restrict__ input_pos, int bsel)
{
    extern __shared__ float sm[];
    float* sq = sm;                   // 64*132
    float* sk = sq + 64 * 132;        // 64*132
    float* sv = sk + 64 * 132;        // 64*36
    float* sA = sv + 64 * 36;         // 64*68
    float* sS = sA + 64 * 68;         // 128*36
    float* sG = sS + 128 * 36;        // 64
    float* sB = sG + 64;              // 64
    float* sW = sB + 64;              // 64

    int bidx = blockIdx.x;            // vs + 4*h
    int vs = bidx & 3;
    int h  = bidx >> 2;
    int b  = bsel;
    int hk = h >> 1;
    int tid = threadIdx.x;
    int tx = tid & 7, ty = tid >> 3;  // tx: 8 col groups, ty: 0..31
    float keep = (input_pos[0] == 0) ? 0.f : 1.f;

    // state rows ty*4..+3; cols tx*4..+3
#pragma unroll
    for (int j = 0; j < 4; j++) {
        int kk = ty * 4 + j;
        float4 v4 = *(const float4*)(rstate + (((size_t)(b * NV_ + h)) * DK_ + kk) * DV_ + vs * DVS + tx * 4);
        v4.x *= keep; v4.y *= keep; v4.z *= keep; v4.w *= keep;
        *(float4*)&sS[kk * 36 + tx * 4] = v4;
    }

    const float* qkBase = g_qk + ((size_t)(b * NHK_ + hk) * NCH) * (LCH * LCH);

    for (int ch = 0; ch < NCH; ch++) {
        int t0 = ch * LCH;
        __syncthreads();
        for (int f = tid; f < 64 * 32; f += 256) {
            int r = f >> 5, c = (f & 31) * 4;
            *(float4*)&sq[r * 132 + c] = *(const float4*)(g_q + (size_t)(b * T_ + t0 + r) * KEY_DIM_ + hk * DK_ + c);
            *(float4*)&sk[r * 132 + c] = *(const float4*)(g_k + (size_t)(b * T_ + t0 + r) * KEY_DIM_ + hk * DK_ + c);
        }
        for (int f = tid; f < 64 * 8; f += 256) {
            int r = f >> 3, c = (f & 7) * 4;
            *(float4*)&sv[r * 36 + c] = *(const float4*)(g_v + (size_t)(b * T_ + t0 + r) * VAL_DIM_ + h * DV_ + vs * DVS + c);
        }
        if (tid < 64) {
            sB[tid] = g_beta[(b * T_ + t0 + tid) * NV_ + h];
            sG[tid] = g_gg  [(b * T_ + t0 + tid) * NV_ + h];
        }
        __syncthreads();
        if (tid == 0) {
            float run = 0.f;
            for (int i = 0; i < LCH; i++) { run += sG[i]; sG[i] = run; }
        }
        __syncthreads();
        if (tid < 64) {
            float df = sG[63] - sG[tid];
            sW[tid] = (df > -30.f) ? expf(df) * sB[tid] : 0.f;
        }

        // sA[t][i] = QK[t][i] * exp(Gt - Gi) * beta_i, masked i<=t. 16 elems/thread.
        {
            const float* qkT = qkBase + (size_t)ch * (LCH * LCH);
#pragma unroll
            for (int half = 0; half < 2; half++) {
                int f0 = (tid * 2 + half) * 8;
                int t = f0 >> 6, i0 = f0 & 63;
                float gt = sG[t];
                float4 qa = *(const float4*)(qkT + t * 64 + i0);
                float4 qb = *(const float4*)(qkT + t * 64 + i0 + 4);
                float r[8] = {qa.x, qa.y, qa.z, qa.w, qb.x, qb.y, qb.z, qb.w};
#pragma unroll
                for (int j = 0; j < 8; j++) {
                    int i = i0 + j;
                    float d = gt - sG[i];
                    r[j] = (i <= t && d > -30.f) ? r[j] * expf(d) * sB[i] : 0.f;
                }
                *(float4*)&sA[t * 68 + i0]     = make_float4(r[0], r[1], r[2], r[3]);
                *(float4*)&sA[t * 68 + i0 + 4] = make_float4(r[4], r[5], r[6], r[7]);
            }
        }
        __syncthreads();

        int r0 = ty * 2, r1 = r0 + 1;
        ull av2[2][2] = {{0ull,0ull},{0ull,0ull}};
        ull ai2[2][2] = {{0ull,0ull},{0ull,0ull}};
        float gr0 = sG[r0];

        // intra: A @ V with causal break (2 rows/thread, 32 cols tile)
        for (int i4 = 0; i4 <= r1; i4 += 4) {
            ull vv0[4], vv1[4];
#pragma unroll
            for (int ii = 0; ii < 4; ii++) {
                vv0[ii] = *(ull*)&sv[(i4 + ii) * 36 + tx * 4];
                vv1[ii] = *(ull*)&sv[(i4 + ii) * 36 + tx * 4 + 2];
            }
#pragma unroll
            for (int a = 0; a < 2; a++) {
                float4 avv = *(float4*)&sA[(r0 + a) * 68 + i4];
                ull s;
                s = bcast2(avv.x); fma2(av2[a][0], s, vv0[0]); fma2(av2[a][1], s, vv1[0]);
                s = bcast2(avv.y); fma2(av2[a][0], s, vv0[1]); fma2(av2[a][1], s, vv1[1]);
                s = bcast2(avv.z); fma2(av2[a][0], s, vv0[2]); fma2(av2[a][1], s, vv1[2]);
                s = bcast2(avv.w); fma2(av2[a][0], s, vv0[3]); fma2(av2[a][1], s, vv1[3]);
            }
        }
        // inter: q @ S (skip when exp(G) negligible)
        if (gr0 > -30.f) {
            for (int k4 = 0; k4 < DK_; k4 += 4) {
                ull s0[4], s1[4];
#pragma unroll
                for (int kk = 0; kk < 4; kk++) {
                    s0[kk] = *(ull*)&sS[(k4 + kk) * 36 + tx * 4];
                    s1[kk] = *(ull*)&sS[(k4 + kk) * 36 + tx * 4 + 2];
                }
#pragma unroll
                for (int a = 0; a < 2; a++) {
                    float4 qa = *(float4*)&sq[(r0 + a) * 132 + k4];
                    ull s;
                    s = bcast2(qa.x); fma2(ai2[a][0], s, s0[0]); fma2(ai2[a][1], s, s1[0]);
                    s = bcast2(qa.y); fma2(ai2[a][0], s, s0[1]); fma2(ai2[a][1], s, s1[1]);
                    s = bcast2(qa.z); fma2(ai2[a][0], s, s0[2]); fma2(ai2[a][1], s, s1[2]);
                    s = bcast2(qa.w); fma2(ai2[a][0], s, s0[3]); fma2(ai2[a][1], s, s1[3]);
                }
            }
        }
#pragma unroll
        for (int a = 0; a < 2; a++) {
            int t = r0 + a;
            ull e2 = bcast2(expf(sG[t]));
            fma2(av2[a][0], e2, ai2[a][0]);
            fma2(av2[a][1], e2, ai2[a][1]);
            float* dst = g_o + (size_t)(b * T_ + t0 + t) * VAL_DIM_ + h * DV_ + vs * DVS + tx * 4;
            *(ull*)dst       = av2[a][0];
            *(ull*)(dst + 2) = av2[a][1];
        }
        __syncthreads();

        // state update: rows ty*4..+3
        ull el2 = bcast2(expf(sG[63]));
        ull S0[4], S1[4];
#pragma unroll
        for (int j = 0; j < 4; j++) {
            S0[j] = *(ull*)&sS[(ty * 4 + j) * 36 + tx * 4];
            S1[j] = *(ull*)&sS[(ty * 4 + j) * 36 + tx * 4 + 2];
            mul2(S0[j], el2); mul2(S1[j], el2);
        }
        for (int i = 0; i < LCH; i++) {
            float w = sW[i];
            if (w == 0.f) continue;
            ull v0 = *(ull*)&sv[i * 36 + tx * 4];
            ull v1 = *(ull*)&sv[i * 36 + tx * 4 + 2];
            float4 k0 = *(float4*)&sk[i * 132 + ty * 4];
            ull s;
            s = bcast2(w * k0.x); fma2(S0[0], s, v0); fma2(S1[0], s, v1);
            s = bcast2(w * k0.y); fma2(S0[1], s, v0); fma2(S1[1], s, v1);
            s = bcast2(w * k0.z); fma2(S0[2], s, v0); fma2(S1[2], s, v1);
            s = bcast2(w * k0.w); fma2(S0[3], s, v0); fma2(S1[3], s, v1);
        }
#pragma unroll
        for (int j = 0; j < 4; j++) {
            *(ull*)&sS[(ty * 4 + j) * 36 + tx * 4]     = S0[j];
            *(ull*)&sS[(ty * 4 + j) * 36 + tx * 4 + 2] = S1[j];
        }
    }
}

// ---------------- gated RMSNorm -> fp16, per-batch ----------------
__global__ void rmsnorm_kernel(const float* __restrict__ norm_w, int btBase)
{
    int bh = blockIdx.x;
    int bt = btBase + (bh >> 5), h = bh & 31;
    int tid = threadIdx.x;
    long idx = (long)bt * VAL_DIM_ + h * DV_ + tid;
    float o = g_o[idx];
    float z = g_z[idx];
    float val = o * (z / (1.f + expf(-z)));
    float s = val * val;
#pragma unroll
    for (int off = 16; off; off >>= 1) s += __shfl_xor_sync(0xffffffffu, s, off);
    __shared__ float red[4];
    int warp = tid >> 5, lane = tid & 31;
    if (lane == 0) red[warp] = s;
    __syncthreads();
    float tot = red[0] + red[1] + red[2] + red[3];
    float scale = rsqrtf(tot * (1.f / 128.f) + 1e-6f) * norm_w[tid];
    g_oh[idx] = __float2half_rn(val * scale);
}

// ---------------- launch: batch-pipelined, 3 streams, records before waits ----------------
extern "C" void kernel_launch(void* const* d_in, const int* in_sizes, int n_in,
                              void* d_out, int out_size)
{
    const float* x          = (const float*)d_in[0];
    const int*   input_pos  = (const int*)  d_in[1];
    const float* W_qkv      = (const float*)d_in[2];
    const float* W_z        = (const float*)d_in[3];
    const float* W_b        = (const float*)d_in[4];
    const float* W_a        = (const float*)d_in[5];
    const float* conv_w     = (const float*)d_in[6];
    const float* dt_bias    = (const float*)d_in[7];
    const float* A_log      = (const float*)d_in[8];
    const float* norm_w     = (const float*)d_in[9];
    const float* W_out      = (const float*)d_in[10];
    const float* conv_state = (const float*)d_in[11];
    const float* rstate     = (const float*)d_in[12];
    float* out = (float*)d_out;

    float *p_qkv, *p_z;
    __half *p_xh, *p_Wqh, *p_Wzh, *p_Woh, *p_oh;
    cudaGetSymbolAddress((void**)&p_qkv, g_qkv);
    cudaGetSymbolAddress((void**)&p_z,   g_z);
    cudaGetSymbolAddress((void**)&p_xh,  g_xh);
    cudaGetSymbolAddress((void**)&p_Wqh, g_Wqh);
    cudaGetSymbolAddress((void**)&p_Wzh, g_Wzh);
    cudaGetSymbolAddress((void**)&p_Woh, g_Woh);
    cudaGetSymbolAddress((void**)&p_oh,  g_oh);

    const int RECUR_SMEM = (64*132*2 + 64*36 + 64*68 + 128*36 + 64*3) * 4;   // 113408 B
    const int QK_SMEM    = (64*132*2) * 4;
    const int HG_SMEM    = 3 * 2 * HSTG * 2;   // 110592 B
    cudaFuncSetAttribute(recur_kernel, cudaFuncAttributeMaxDynamicSharedMemorySize, RECUR_SMEM);
    cudaFuncSetAttribute(qk_kernel,    cudaFuncAttributeMaxDynamicSharedMemorySize, QK_SMEM);
    cudaFuncSetAttribute(hgemm_nt,     cudaFuncAttributeMaxDynamicSharedMemorySize, HG_SMEM);

    static cudaStream_t sZ = nullptr, sBA = nullptr;
    static cudaEvent_t evRoot, evX, evQ0, evBA, evZ0, evZ1, evP0;
    if (!sZ) {
        cudaStreamCreateWithFlags(&sZ,  cudaStreamNonBlocking);
        cudaStreamCreateWithFlags(&sBA, cudaStreamNonBlocking);
        cudaEventCreateWithFlags(&evRoot, cudaEventDisableTiming);
        cudaEventCreateWithFlags(&evX,    cudaEventDisableTiming);
        cudaEventCreateWithFlags(&evQ0,   cudaEventDisableTiming);
        cudaEventCreateWithFlags(&evBA,   cudaEventDisableTiming);
        cudaEventCreateWithFlags(&evZ0,   cudaEventDisableTiming);
        cudaEventCreateWithFlags(&evZ1,   cudaEventDisableTiming);
        cudaEventCreateWithFlags(&evP0,   cudaEventDisableTiming);
    }

    // ---- fork ----
    cudaEventRecord(evRoot, 0);
    cudaStreamWaitEvent(sZ,  evRoot, 0);
    cudaStreamWaitEvent(sBA, evRoot, 0);

    // 1) main: cvt(x, Wq) -> qkv_b0 -> qkv_b1 (records evX, evQ0)
    cvt2<<<((BT_*C_/4 + CONV_DIM_*C_/4) + 255)/256, 256>>>(x, p_xh, BT_*C_/4, W_qkv, p_Wqh, CONV_DIM_*C_/4);
    cudaEventRecord(evX, 0);
    hgemm_nt<<<dim3(CONV_DIM_/128, T_/128), 256, HG_SMEM>>>(p_xh, p_Wqh, p_qkv, CONV_DIM_, C_, 0);
    cudaEventRecord(evQ0, 0);
    hgemm_nt<<<dim3(CONV_DIM_/128, T_/128), 256, HG_SMEM>>>(p_xh, p_Wqh, p_qkv, CONV_DIM_, C_, T_);

    // 2) sZ branch: cvt(Wz, Wo) -> z_b0 -> z_b1 (records evZ0, evZ1)
    cvt2<<<((VAL_DIM_*C_/4 + C_*VAL_DIM_/4) + 255)/256, 256, 0, sZ>>>(W_z, p_Wzh, VAL_DIM_*C_/4, W_out, p_Woh, C_*VAL_DIM_/4);
    cudaStreamWaitEvent(sZ, evX, 0);
    hgemm_nt<<<dim3(VAL_DIM_/128, T_/128), 256, HG_SMEM, sZ>>>(p_xh, p_Wzh, p_z, VAL_DIM_, C_, 0);
    cudaEventRecord(evZ0, sZ);
    hgemm_nt<<<dim3(VAL_DIM_/128, T_/128), 256, HG_SMEM, sZ>>>(p_xh, p_Wzh, p_z, VAL_DIM_, C_, T_);
    cudaEventRecord(evZ1, sZ);

    // 3) sBA branch: ba GEMM (+beta/g) -> evBA -> batch-0 pipeline -> evP0
    sgemm_ba_fused<<<dim3(1, BT_/128), 256, 0, sBA>>>(x, W_b, W_a, dt_bias, A_log);
    cudaEventRecord(evBA, sBA);
    cudaStreamWaitEvent(sBA, evQ0, 0);
    conv_kernel<<<T_/CTT, 512, 0, sBA>>>(conv_w, conv_state, input_pos, 0);
    qk_kernel<<<NHK_ * NCH, 256, QK_SMEM, sBA>>>(0);
    recur_kernel<<<NV_ * SPLITV, 256, RECUR_SMEM, sBA>>>(rstate, input_pos, 0);
    cudaStreamWaitEvent(sBA, evZ0, 0);
    rmsnorm_kernel<<<T_ * NV_, 128, 0, sBA>>>(norm_w, 0);
    hgemm_nt<<<dim3(C_/128, T_/128), 256, HG_SMEM, sBA>>>(p_oh, p_Woh, out, C_, VAL_DIM_, 0);
    cudaEventRecord(evP0, sBA);

    // 4) main: batch-1 chain (all waited events recorded above)
    conv_kernel<<<T_/CTT, 512>>>(conv_w, conv_state, input_pos, 1);
    qk_kernel<<<NHK_ * NCH, 256, QK_SMEM>>>(1);
    cudaStreamWaitEvent(0, evBA, 0);
    recur_kernel<<<NV_ * SPLITV, 256, RECUR_SMEM>>>(rstate, input_pos, 1);
    cudaStreamWaitEvent(0, evZ1, 0);
    rmsnorm_kernel<<<T_ * NV_, 128>>>(norm_w, T_);
    hgemm_nt<<<dim3(C_/128, T_/128), 256, HG_SMEM>>>(p_oh, p_Woh, out, C_, VAL_DIM_, T_);

    // 5) join batch-0 pipeline back to main
    cudaStreamWaitEvent(0, evP0, 0);
}